// round 7
// baseline (speedup 1.0000x reference)
#include <cuda_runtime.h>

// B=8192, T=2048, H=51
#define B_   8192
#define T_   2048
#define H_   51
#define CP   208           // 52*4 gate-interleaved columns (u=51 is zero pad)
#define M_   64
#define NTH  512

typedef unsigned long long u64;

__device__ __forceinline__ u64 pack2(float lo, float hi) {
    u64 d; asm("mov.b64 %0, {%1, %2};" : "=l"(d) : "f"(lo), "f"(hi)); return d;
}
__device__ __forceinline__ void unpack2(u64 v, float& lo, float& hi) {
    asm("mov.b64 {%0, %1}, %2;" : "=f"(lo), "=f"(hi) : "l"(v));
}
__device__ __forceinline__ u64 fma2(u64 a, u64 b, u64 c) {
    u64 d; asm("fma.rn.f32x2 %0, %1, %2, %3;" : "=l"(d) : "l"(a), "l"(b), "l"(c)); return d;
}
__device__ __forceinline__ float ex2f(float x) { float r; asm("ex2.approx.f32 %0, %1;" : "=f"(r) : "f"(x)); return r; }
__device__ __forceinline__ float rcpf(float x) { float r; asm("rcp.approx.f32 %0, %1;" : "=f"(r) : "f"(x)); return r; }
__device__ __forceinline__ float sigm(float x) {
    return rcpf(1.0f + ex2f(-1.4426950408889634f * x));
}
__device__ __forceinline__ float tanh_(float x) {
    float e = ex2f(2.8853900817779268f * x);
    return 1.0f - 2.0f * rcpf(e + 1.0f);
}

// Smem layout (float offsets)
#define OFF_W1   0           // [51][208]
#define OFF_W2A  10608
#define OFF_W2B  21216
#define OFF_H1D  31824       // double buffer [2][52][128] duplicated (h,h)
#define OFF_H2D  45136       // single buffer [52][128] duplicated (h,h)
#define OFF_B1   51792
#define OFF_WI1  52000
#define OFF_B2   52208
#define OFF_WL   52416       // 56
#define OFF_YP   52472       // [2][4][64]
#define SMEM_FLOATS 52984    // ~207 KB

#define HB1 6656             // 52*128

__global__ __launch_bounds__(NTH, 1)
void lstm_rnn_kernel(const float* __restrict__ x,
                     const float* __restrict__ Wih1, const float* __restrict__ Whh1,
                     const float* __restrict__ bih1, const float* __restrict__ bhh1,
                     const float* __restrict__ Wih2, const float* __restrict__ Whh2,
                     const float* __restrict__ bih2, const float* __restrict__ bhh2,
                     const float* __restrict__ Wlin, const float* __restrict__ blin,
                     float* __restrict__ out)
{
    extern __shared__ float sm[];
    float* W1s  = sm + OFF_W1;
    float* W2as = sm + OFF_W2A;
    float* W2bs = sm + OFF_W2B;
    float* H1D  = sm + OFF_H1D;
    float* H2D  = sm + OFF_H2D;
    float* B1s  = sm + OFF_B1;
    float* WI1s = sm + OFF_WI1;
    float* B2s  = sm + OFF_B2;
    float* WLs  = sm + OFF_WL;
    float* YP   = sm + OFF_YP;

    const int tid = threadIdx.x;

    // ---- stage weights gate-interleaved, k-major: W[k][u*4+g] = Wxx[g*51+u][k]
    for (int idx = tid; idx < H_ * CP; idx += NTH) {
        int kk = idx / CP, c = idx - kk * CP;
        int u = c >> 2, g = c & 3;
        float w1 = 0.f, wa = 0.f, wb = 0.f;
        if (u < H_) {
            int j = g * H_ + u;
            w1 = Whh1[j * H_ + kk];
            wa = Wih2[j * H_ + kk];
            wb = Whh2[j * H_ + kk];
        }
        W1s[idx] = w1; W2as[idx] = wa; W2bs[idx] = wb;
    }
    for (int c = tid; c < CP; c += NTH) {
        int u = c >> 2, g = c & 3;
        bool v = (u < H_);
        int j = g * H_ + u;
        B1s[c]  = v ? (bih1[j] + bhh1[j]) : 0.f;
        WI1s[c] = v ? Wih1[j] : 0.f;
        B2s[c]  = v ? (bih2[j] + bhh2[j]) : 0.f;
    }
    if (tid < 53) WLs[tid] = (tid < H_) ? Wlin[tid] : ((tid == 52) ? blin[0] : 0.f);
    for (int idx = tid; idx < 2 * HB1; idx += NTH) H1D[idx] = 0.f;
    for (int idx = tid; idx < HB1; idx += NTH)     H2D[idx] = 0.f;
    for (int idx = tid; idx < 512; idx += NTH) YP[idx] = 0.f;
    __syncthreads();

    // roles: threads 0-255 (grp0) = layer 1 + y writer; 256-511 (grp1) = layer 2
    const int grp = tid >> 8;
    const int lt  = tid & 255;
    const int ug  = lt >> 6;         // 0..3, warp-uniform: u slice [ug*13, ug*13+13)
    const int m   = lt & 63;         // one batch row per thread
    const int cb  = ug * 52;         // float offset of 52-col gate slice
    const int hoff = m * 2;          // duplicated-h float offset
    const int m0  = blockIdx.x * M_;

    u64 acc[26];                     // 52 gate columns (1 m-row)
    float cr[13];                    // c state for this thread's 13 cells
#pragma unroll
    for (int q = 0; q < 13; ++q) cr[q] = 0.f;

    float xn = 0.f;

    // ---- prologue (grp0): gates1(0) = b1 + x(0)*Wih1  (h1(-1)=0) ----
    if (grp == 0) {
        float x0 = x[(size_t)(m0 + m) * T_];
        u64 xd = pack2(x0, x0);
        const ulonglong2* Bp = (const ulonglong2*)(B1s + cb);
        const ulonglong2* Wp = (const ulonglong2*)(WI1s + cb);
#pragma unroll
        for (int q = 0; q < 13; ++q) {
            ulonglong2 b2 = Bp[q], w2 = Wp[q];
            acc[2*q+0] = fma2(xd, w2.x, b2.x);
            acc[2*q+1] = fma2(xd, w2.y, b2.y);
        }
    }

    for (int i = 0; i <= T_; ++i) {
        // ================= Segment A =================
        if (grp == 0) {
            // prefetch x(i+1)
            int tn = (i + 1 < T_) ? (i + 1) : (T_ - 1);
            xn = x[(size_t)(m0 + m) * T_ + tn];
            // y writer: step i-2 (partials written in segB(i-1) into buffer i&1)
            if (lt < 64 && i >= 2) {
                const float* yp = YP + (i & 1) * 256;
                float y = WLs[52] + yp[lt] + yp[64 + lt] + yp[128 + lt] + yp[192 + lt];
                out[(size_t)(m0 + lt) * T_ + (i - 2)] = y;
            }
            // activation layer1, step i -> h1(i)  (dup layout, buffer i&1)
            if (i < T_) {
                float* Hw = H1D + (i & 1) * HB1;
#pragma unroll
                for (int q = 0; q < 13; ++q) {
                    float iv, fv, gv, ov;
                    unpack2(acc[2*q+0], iv, fv);
                    unpack2(acc[2*q+1], gv, ov);
                    float c = sigm(fv) * cr[q] + sigm(iv) * tanh_(gv);
                    cr[q] = c;
                    float hh = sigm(ov) * tanh_(c);
                    *(float2*)(Hw + (ug * 13 + q) * 128 + hoff) = make_float2(hh, hh);
                }
            }
        } else {
            // GEMM layer2, step i-1: Wih2*h1(i-1) + Whh2*h2(i-2) + b2
            if (i >= 1) {
                {
                    const ulonglong2* Bp = (const ulonglong2*)(B2s + cb);
#pragma unroll
                    for (int q = 0; q < 13; ++q) {
                        ulonglong2 b2 = Bp[q];
                        acc[2*q+0] = b2.x; acc[2*q+1] = b2.y;
                    }
                }
                const float* H1r = H1D + ((i - 1) & 1) * HB1;   // h1(i-1) dup
                const float* H2r = H2D;                          // h2(i-2) dup
                const float* wa0 = W2as + cb;
                const float* wb0 = W2bs + cb;
#pragma unroll 3
                for (int kk = 0; kk < H_; ++kk) {
                    u64 ha = *(const u64*)(H1r + kk * 128 + hoff);
                    u64 hb = *(const u64*)(H2r + kk * 128 + hoff);
                    const ulonglong2* wra = (const ulonglong2*)(wa0 + kk * CP);
                    const ulonglong2* wrb = (const ulonglong2*)(wb0 + kk * CP);
#pragma unroll
                    for (int q = 0; q < 13; ++q) {
                        ulonglong2 wa = wra[q];
                        acc[2*q+0] = fma2(ha, wa.x, acc[2*q+0]);
                        acc[2*q+1] = fma2(ha, wa.y, acc[2*q+1]);
                        ulonglong2 wb = wrb[q];
                        acc[2*q+0] = fma2(hb, wb.x, acc[2*q+0]);
                        acc[2*q+1] = fma2(hb, wb.y, acc[2*q+1]);
                    }
                }
            }
        }
        __syncthreads();

        // ================= Segment B =================
        if (grp == 0) {
            // GEMM layer1, step i+1: Whh1*h1(i) + x(i+1)*Wih1 + b1
            if (i + 1 < T_) {
                {
                    u64 xd = pack2(xn, xn);
                    const ulonglong2* Bp = (const ulonglong2*)(B1s + cb);
                    const ulonglong2* Wp = (const ulonglong2*)(WI1s + cb);
#pragma unroll
                    for (int q = 0; q < 13; ++q) {
                        ulonglong2 b2 = Bp[q], w2 = Wp[q];
                        acc[2*q+0] = fma2(xd, w2.x, b2.x);
                        acc[2*q+1] = fma2(xd, w2.y, b2.y);
                    }
                }
                const float* Hr  = H1D + (i & 1) * HB1;          // h1(i) dup
                const float* wb0 = W1s + cb;
#pragma unroll 3
                for (int kk = 0; kk < H_; ++kk) {
                    u64 hv = *(const u64*)(Hr + kk * 128 + hoff);
                    const ulonglong2* wr = (const ulonglong2*)(wb0 + kk * CP);
#pragma unroll
                    for (int q = 0; q < 13; ++q) {
                        ulonglong2 w2 = wr[q];
                        acc[2*q+0] = fma2(hv, w2.x, acc[2*q+0]);
                        acc[2*q+1] = fma2(hv, w2.y, acc[2*q+1]);
                    }
                }
            }
        } else {
            // activation layer2, step i-1 -> h2(i-1) (dup), y partials
            if (i >= 1) {
                float py = 0.f;
#pragma unroll
                for (int q = 0; q < 13; ++q) {
                    float iv, fv, gv, ov;
                    unpack2(acc[2*q+0], iv, fv);
                    unpack2(acc[2*q+1], gv, ov);
                    float c = sigm(fv) * cr[q] + sigm(iv) * tanh_(gv);
                    cr[q] = c;
                    float hh = sigm(ov) * tanh_(c);
                    *(float2*)(H2D + (ug * 13 + q) * 128 + hoff) = make_float2(hh, hh);
                    py = fmaf(WLs[ug * 13 + q], hh, py);
                }
                YP[((i - 1) & 1) * 256 + ug * 64 + m] = py;
            }
        }
        __syncthreads();
    }

    // final y for step T-1 (partials in buffer (T-1)&1)
    if (tid < 64) {
        const float* yp = YP + ((T_ - 1) & 1) * 256;
        float y = WLs[52] + yp[tid] + yp[64 + tid] + yp[128 + tid] + yp[192 + tid];
        out[(size_t)(m0 + tid) * T_ + (T_ - 1)] = y;
    }
}

extern "C" void kernel_launch(void* const* d_in, const int* in_sizes, int n_in,
                              void* d_out, int out_size) {
    const float* x    = (const float*)d_in[0];
    const float* Wih1 = (const float*)d_in[1];
    const float* Whh1 = (const float*)d_in[2];
    const float* bih1 = (const float*)d_in[3];
    const float* bhh1 = (const float*)d_in[4];
    const float* Wih2 = (const float*)d_in[5];
    const float* Whh2 = (const float*)d_in[6];
    const float* bih2 = (const float*)d_in[7];
    const float* bhh2 = (const float*)d_in[8];
    const float* Wlin = (const float*)d_in[9];
    const float* blin = (const float*)d_in[10];
    float* out = (float*)d_out;

    size_t smem = SMEM_FLOATS * sizeof(float);   // ~207 KB
    cudaFuncSetAttribute(lstm_rnn_kernel,
                         cudaFuncAttributeMaxDynamicSharedMemorySize, (int)smem);
    lstm_rnn_kernel<<<B_ / M_, NTH, smem>>>(x, Wih1, Whh1, bih1, bhh1,
                                            Wih2, Whh2, bih2, bhh2,
                                            Wlin, blin, out);
}